// round 14
// baseline (speedup 1.0000x reference)
#include <cuda_runtime.h>
#include <cuda_fp16.h>
#include <cstdint>

// ---------------- problem constants ----------------
#define DF    64
#define HHn   8
#define HD    512
#define G3    1536
#define NODES_MAX 100000
#define E_MAX     100000
#define ND_MAX    50000

// ---------------- device scratch ----------------
__device__ float g_F[(size_t)NODES_MAX * G3];     // x@Wih^T + b_ih (fp32)
__device__ float g_h[(size_t)E_MAX * HD];         // fp32 hidden state (in-place)
__device__ __half g_Xh[(size_t)NODES_MAX * DF];   // feature splits (F-GEMM, 3-term)
__device__ __half g_Xl[(size_t)NODES_MAX * DF];
__device__ __half g_Ah0[(size_t)E_MAX * HD];      // fl16(h) ping
__device__ __half g_Ah1[(size_t)E_MAX * HD];      // fl16(h) pong
__device__ __half g_Bhh[(size_t)G3 * HD];         // fl16(Whh) (1.5 MB, L2-resident)
__device__ __half g_Bih[(size_t)G3 * (3 * DF)];   // Wih packed [Wh|Wl|Wh]
__device__ float g_aexp[(size_t)E_MAX * HHn];
__device__ float g_asum[(size_t)ND_MAX * HHn];

// ---------------- helpers ----------------
__device__ __forceinline__ uint32_t smem_u32(const void* p) {
    uint32_t a;
    asm("{ .reg .u64 t; cvta.to.shared.u64 t, %1; cvt.u32.u64 %0, t; }"
        : "=r"(a) : "l"(p));
    return a;
}
__device__ __forceinline__ void cp16(uint32_t s, const void* g) {
    asm volatile("cp.async.cg.shared.global [%0], [%1], 16;" :: "r"(s), "l"(g));
}
__device__ __forceinline__ void cp_commit() {
    asm volatile("cp.async.commit_group;" ::: "memory");
}
template<int N>
__device__ __forceinline__ void cp_wait() {
    asm volatile("cp.async.wait_group %0;" :: "n"(N) : "memory");
}
__device__ __forceinline__ void ldsm4(uint32_t& r0, uint32_t& r1, uint32_t& r2,
                                      uint32_t& r3, uint32_t addr) {
    asm volatile("ldmatrix.sync.aligned.m8n8.x4.shared.b16 {%0,%1,%2,%3}, [%4];"
                 : "=r"(r0), "=r"(r1), "=r"(r2), "=r"(r3) : "r"(addr));
}
// f32-accumulate HMMA (used in fgemm for precision)
__device__ __forceinline__ void mma16816(float* c, const uint32_t* a,
                                         uint32_t b0, uint32_t b1) {
    asm volatile("mma.sync.aligned.m16n8k16.row.col.f32.f16.f16.f32 "
                 "{%0,%1,%2,%3}, {%4,%5,%6,%7}, {%8,%9}, {%0,%1,%2,%3};"
                 : "+f"(c[0]), "+f"(c[1]), "+f"(c[2]), "+f"(c[3])
                 : "r"(a[0]), "r"(a[1]), "r"(a[2]), "r"(a[3]), "r"(b0), "r"(b1));
}
// f16-accumulate HMMA (step GEMMs): d = {half2 row gq, half2 row gq+8}
__device__ __forceinline__ void mma16816h(uint32_t& d0, uint32_t& d1,
                                          const uint32_t* a,
                                          uint32_t b0, uint32_t b1) {
    asm volatile("mma.sync.aligned.m16n8k16.row.col.f16.f16.f16.f16 "
                 "{%0,%1}, {%2,%3,%4,%5}, {%6,%7}, {%0,%1};"
                 : "+r"(d0), "+r"(d1)
                 : "r"(a[0]), "r"(a[1]), "r"(a[2]), "r"(a[3]), "r"(b0), "r"(b1));
}
__device__ __forceinline__ float2 ld2f(const float* p) { return *reinterpret_cast<const float2*>(p); }
__device__ __forceinline__ float4 ld4(const float* p)  { return *reinterpret_cast<const float4*>(p); }
__device__ __forceinline__ float sigmf(float x) { return __fdividef(1.0f, 1.0f + __expf(-x)); }
__device__ __forceinline__ float tanhfast(float x) {
    return 1.0f - __fdividef(2.0f, __expf(2.0f * x) + 1.0f);
}
__device__ __forceinline__ float gru_one(float fr, float gr, float fz, float gz,
                                         float fn, float gn, float hp) {
    float r = sigmf(fr + gr);
    float z = sigmf(fz + gz);
    float n = tanhfast(fn + r * gn);
    return n + z * (hp - n);
}
__device__ __forceinline__ void split_f16(float x, unsigned short& hi, unsigned short& lo) {
    __half h = __float2half_rn(x);
    __half l = __float2half_rn(x - __half2float(h));
    hi = __half_as_ushort(h);
    lo = __half_as_ushort(lo = __half_as_ushort(l));
    lo = __half_as_ushort(l);
}

// ================= step GEMM: f16-acc HMMA, single-sync pipeline =================
// 256 threads, 8 warps (4m x 2n). CTA tile: 128 rows x 64 cols x 3 gates. K'=512.
// A = fl16(h) [M,512]; B = fl16(Whh) [1536,512]. KTILE=64, T=8, depth-2 cp.async.
// Epilogue: fused GRU gates; fp32 hstate updated in place;
// MODE 1 additionally writes fl16(h_new) for the next step's A.
#define SHS    72                        // smem row stride (halves), 144 B
#define SABUF  (128 * SHS * 2)           // 18432 B
#define SBUF   (320 * SHS * 2)           // 46080 B
#define SSMEM  (2 * SBUF)                // 92160 B -> 2 CTAs/SM

template<int MODE>
__global__ void __launch_bounds__(256, 2)
step_gemm(const __half* __restrict__ Ain,
          const __half* __restrict__ Bp,
          const float* __restrict__ bias,
          const int* __restrict__ mp,
          float* __restrict__ hstate,
          __half* __restrict__ oA,
          int M, int t)
{
    extern __shared__ char sm[];
    const uint32_t sbase = smem_u32(sm);

    const int tid  = threadIdx.x;
    const int wid  = tid >> 5;
    const int lane = tid & 31;
    const int nb   = blockIdx.x * 64;
    const int mb   = blockIdx.y * 128;
    const int wq = wid >> 1;             // m quarter
    const int wn = wid & 1;              // n half (32 cols)

    // f16 accumulators: [gate][ma][n8-group][row-half], each u32 = half2
    uint32_t acch[3][2][4][2];
    #pragma unroll
    for (int g = 0; g < 3; ++g)
        #pragma unroll
        for (int i = 0; i < 2; ++i)
            #pragma unroll
            for (int j = 0; j < 4; ++j) { acch[g][i][j][0] = 0u; acch[g][i][j][1] = 0u; }

    auto stage = [&](int kt) {
        const uint32_t ab = sbase + (kt & 1) * SBUF;
        const int kcol = kt * 64;
        #pragma unroll
        for (int it = 0; it < 10; ++it) {
            int i = tid + it * 256;      // 0..2559 (320 rows x 8 chunks)
            if (i < 1024) {
                int row = i >> 3, c = i & 7;
                int gr = mb + row; if (gr >= M) gr = M - 1;
                cp16(ab + (row * SHS + c * 8) * 2, &Ain[(size_t)gr * HD + kcol + c * 8]);
            } else {
                int j = i - 1024;
                int lr = j >> 3, c = j & 7;
                int grow = (lr >> 6) * 512 + nb + (lr & 63);
                cp16(ab + SABUF + (lr * SHS + c * 8) * 2,
                     &Bp[(size_t)grow * HD + kcol + c * 8]);
            }
        }
        cp_commit();
    };

    stage(0);
    for (int kt = 0; kt < 8; ++kt) {
        cp_wait<0>();                 // stage(kt) complete (issued one iter ago)
        __syncthreads();              // all warps done reading buffer (kt-1)
        if (kt + 1 < 8) stage(kt + 1);  // safe: overwrites buffer (kt-1)

        const uint32_t ab = sbase + (kt & 1) * SBUF;
        const uint32_t bb = ab + SABUF;
        const int lr16 = lane & 15;
        const int koff = (lane >> 4) << 3;

        #pragma unroll
        for (int kk = 0; kk < 64; kk += 16) {
            uint32_t af[2][4];
            #pragma unroll
            for (int ma = 0; ma < 2; ++ma) {
                uint32_t a = ab + ((wq * 32 + ma * 16 + lr16) * SHS + kk + koff) * 2;
                ldsm4(af[ma][0], af[ma][1], af[ma][2], af[ma][3], a);
            }
            #pragma unroll
            for (int g = 0; g < 3; ++g) {
                #pragma unroll
                for (int np = 0; np < 2; ++np) {
                    uint32_t b0, b1, b2, b3;
                    uint32_t a = bb + ((g * 64 + wn * 32 + np * 16 + lr16) * SHS
                                       + kk + koff) * 2;
                    ldsm4(b0, b1, b2, b3, a);
                    #pragma unroll
                    for (int ma = 0; ma < 2; ++ma) {
                        mma16816h(acch[g][ma][np * 2 + 0][0], acch[g][ma][np * 2 + 0][1],
                                  af[ma], b0, b2);
                        mma16816h(acch[g][ma][np * 2 + 1][0], acch[g][ma][np * 2 + 1][1],
                                  af[ma], b1, b3);
                    }
                }
            }
        }
    }
    __syncthreads();   // protect epilogue ordering (no buffer hazard after loop)

    // ---- fused GRU epilogue ----
    const int gq  = lane >> 2;
    const int tig = lane & 3;
    #pragma unroll
    for (int ma = 0; ma < 2; ++ma) {
        #pragma unroll
        for (int p = 0; p < 2; ++p) {
            const int m = mb + wq * 32 + ma * 16 + gq + p * 8;
            if (m >= M) continue;
            const int node = mp[m * 3 + t];
            const float* Fp = &g_F[(size_t)node * G3];
            #pragma unroll
            for (int na = 0; na < 4; ++na) {
                const int j = nb + wn * 32 + na * 8 + tig * 2;
                float2 vr = __half22float2(*reinterpret_cast<__half2*>(&acch[0][ma][na][p]));
                float2 vz = __half22float2(*reinterpret_cast<__half2*>(&acch[1][ma][na][p]));
                float2 vn = __half22float2(*reinterpret_cast<__half2*>(&acch[2][ma][na][p]));
                float2 br = ld2f(&bias[j]);
                float2 bz = ld2f(&bias[512 + j]);
                float2 bn = ld2f(&bias[1024 + j]);
                float2 fr = ld2f(&Fp[j]);
                float2 fz = ld2f(&Fp[512 + j]);
                float2 fn = ld2f(&Fp[1024 + j]);
                float2 hp = ld2f(&hstate[(size_t)m * HD + j]);
                float h0 = gru_one(fr.x, vr.x + br.x, fz.x, vz.x + bz.x,
                                   fn.x, vn.x + bn.x, hp.x);
                float h1 = gru_one(fr.y, vr.y + br.y, fz.y, vz.y + bz.y,
                                   fn.y, vn.y + bn.y, hp.y);
                *reinterpret_cast<float2*>(&hstate[(size_t)m * HD + j]) =
                    make_float2(h0, h1);
                if (MODE == 1) {
                    ushort2 oh;
                    oh.x = __half_as_ushort(__float2half_rn(h0));
                    oh.y = __half_as_ushort(__float2half_rn(h1));
                    *reinterpret_cast<ushort2*>(&oA[(size_t)m * HD + j]) = oh;
                }
            }
        }
    }
}

// ================= F-GEMM (3-term fp16, f32-acc): F = x @ Wih^T + b_ih =================
#define FHS    72
#define FABUF  (128 * FHS * 2)
#define FBUFB  (320 * FHS * 2)
#define FSMEM  (2 * FBUFB)

__global__ void __launch_bounds__(256, 2)
fgemm(const __half* __restrict__ Xh,
      const __half* __restrict__ Xl,
      const __half* __restrict__ Bp,
      const float* __restrict__ bias,
      float* __restrict__ outF, int M)
{
    extern __shared__ char sm[];
    const uint32_t sbase = smem_u32(sm);

    const int tid  = threadIdx.x;
    const int wid  = tid >> 5;
    const int lane = tid & 31;
    const int nb   = blockIdx.x * 64;
    const int mb   = blockIdx.y * 128;
    const int wq = wid >> 1;
    const int wn = wid & 1;

    float acc[3][2][4][4];
    #pragma unroll
    for (int g = 0; g < 3; ++g)
        #pragma unroll
        for (int i = 0; i < 2; ++i)
            #pragma unroll
            for (int j = 0; j < 4; ++j)
                #pragma unroll
                for (int c = 0; c < 4; ++c) acc[g][i][j][c] = 0.f;

    auto stage = [&](int kt) {
        const __half* As = (kt == 2) ? Xl : Xh;
        const uint32_t ab = sbase + (kt & 1) * FBUFB;
        #pragma unroll
        for (int it = 0; it < 10; ++it) {
            int i = tid + it * 256;
            if (i < 1024) {
                int row = i >> 3, c = i & 7;
                int gr = mb + row; if (gr >= M) gr = M - 1;
                cp16(ab + (row * FHS + c * 8) * 2, &As[(size_t)gr * DF + c * 8]);
            } else {
                int j = i - 1024;
                int lr = j >> 3, c = j & 7;
                int grow = (lr >> 6) * 512 + nb + (lr & 63);
                cp16(ab + FABUF + (lr * FHS + c * 8) * 2,
                     &Bp[(size_t)grow * 192 + kt * 64 + c * 8]);
            }
        }
        cp_commit();
    };

    stage(0);
    for (int kt = 0; kt < 3; ++kt) {
        cp_wait<0>();
        __syncthreads();
        if (kt + 1 < 3) stage(kt + 1);
        const uint32_t ab = sbase + (kt & 1) * FBUFB;
        const uint32_t bb = ab + FABUF;
        const int lr16 = lane & 15;
        const int koff = (lane >> 4) << 3;
        #pragma unroll
        for (int kk = 0; kk < 64; kk += 16) {
            uint32_t af[2][4];
            #pragma unroll
            for (int ma = 0; ma < 2; ++ma) {
                uint32_t a = ab + ((wq * 32 + ma * 16 + lr16) * FHS + kk + koff) * 2;
                ldsm4(af[ma][0], af[ma][1], af[ma][2], af[ma][3], a);
            }
            #pragma unroll
            for (int g = 0; g < 3; ++g) {
                #pragma unroll
                for (int np = 0; np < 2; ++np) {
                    uint32_t b0, b1, b2, b3;
                    uint32_t a = bb + ((g * 64 + wn * 32 + np * 16 + lr16) * FHS
                                       + kk + koff) * 2;
                    ldsm4(b0, b1, b2, b3, a);
                    #pragma unroll
                    for (int ma = 0; ma < 2; ++ma) {
                        mma16816(acc[g][ma][np * 2 + 0], af[ma], b0, b2);
                        mma16816(acc[g][ma][np * 2 + 1], af[ma], b1, b3);
                    }
                }
            }
        }
    }

    const int gq  = lane >> 2;
    const int tig = lane & 3;
    #pragma unroll
    for (int ma = 0; ma < 2; ++ma) {
        #pragma unroll
        for (int p = 0; p < 2; ++p) {
            const int m = mb + wq * 32 + ma * 16 + gq + p * 8;
            if (m >= M) continue;
            #pragma unroll
            for (int na = 0; na < 4; ++na) {
                const int j = nb + wn * 32 + na * 8 + tig * 2;
                float2 br = ld2f(&bias[j]);
                float2 bz = ld2f(&bias[512 + j]);
                float2 bn = ld2f(&bias[1024 + j]);
                *reinterpret_cast<float2*>(&outF[(size_t)m * G3 + j]) =
                    make_float2(acc[0][ma][na][p*2] + br.x, acc[0][ma][na][p*2+1] + br.y);
                *reinterpret_cast<float2*>(&outF[(size_t)m * G3 + 512 + j]) =
                    make_float2(acc[1][ma][na][p*2] + bz.x, acc[1][ma][na][p*2+1] + bz.y);
                *reinterpret_cast<float2*>(&outF[(size_t)m * G3 + 1024 + j]) =
                    make_float2(acc[2][ma][na][p*2] + bn.x, acc[2][ma][na][p*2+1] + bn.y);
            }
        }
    }
}

// ================= elementwise kernels =================
__global__ void zero_kernel(float* __restrict__ out, int nOut, int nSum) {
    int stride = gridDim.x * blockDim.x;
    int i0 = blockIdx.x * blockDim.x + threadIdx.x;
    for (int i = i0; i < nOut; i += stride) out[i] = 0.0f;
    for (int i = i0; i < nSum; i += stride) g_asum[i] = 0.0f;
}

__global__ void split_kernel(const float* __restrict__ feat,
                             const float* __restrict__ Whh,
                             const float* __restrict__ Wih, int nodes) {
    int stride = gridDim.x * blockDim.x;
    int i0 = blockIdx.x * blockDim.x + threadIdx.x;
    for (int i = i0; i < nodes * DF; i += stride) {
        unsigned short hi, lo;
        __half h = __float2half_rn(feat[i]);
        __half l = __float2half_rn(feat[i] - __half2float(h));
        hi = __half_as_ushort(h); lo = __half_as_ushort(l);
        g_Xh[i] = __ushort_as_half(hi);
        g_Xl[i] = __ushort_as_half(lo);
    }
    for (int i = i0; i < G3 * HD; i += stride)
        g_Bhh[i] = __float2half_rn(Whh[i]);
    for (int i = i0; i < G3 * DF; i += stride) {
        int n = i >> 6, k = i & 63;
        __half h = __float2half_rn(Wih[i]);
        __half l = __float2half_rn(Wih[i] - __half2float(h));
        size_t b = (size_t)n * (3 * DF);
        g_Bih[b + k]       = h;
        g_Bih[b + 64 + k]  = l;
        g_Bih[b + 128 + k] = h;
    }
}

// step 0: h1 = gru(F[node0], b_hh, h=0); write fp32 g_h + fp16 g_Ah0
__global__ void step0_kernel(const int* __restrict__ mp,
                             const float* __restrict__ bhh, int E) {
    int i = blockIdx.x * blockDim.x + threadIdx.x;
    if (i >= E * (HD / 4)) return;
    int e = i >> 7, c4 = (i & 127) << 2;
    int node = mp[e * 3];
    const float* Fp = &g_F[(size_t)node * G3];
    float4 fr = ld4(Fp + c4), fz = ld4(Fp + 512 + c4), fn = ld4(Fp + 1024 + c4);
    float4 br = ld4(bhh + c4), bz = ld4(bhh + 512 + c4), bn = ld4(bhh + 1024 + c4);
    float h0 = gru_one(fr.x, br.x, fz.x, bz.x, fn.x, bn.x, 0.f);
    float h1 = gru_one(fr.y, br.y, fz.y, bz.y, fn.y, bn.y, 0.f);
    float h2 = gru_one(fr.z, br.z, fz.z, bz.z, fn.z, bn.z, 0.f);
    float h3 = gru_one(fr.w, br.w, fz.w, bz.w, fn.w, bn.w, 0.f);
    *reinterpret_cast<float4*>(&g_h[(size_t)e * HD + c4]) = make_float4(h0, h1, h2, h3);
    ushort4 oh;
    oh.x = __half_as_ushort(__float2half_rn(h0));
    oh.y = __half_as_ushort(__float2half_rn(h1));
    oh.z = __half_as_ushort(__float2half_rn(h2));
    oh.w = __half_as_ushort(__float2half_rn(h3));
    *reinterpret_cast<ushort4*>(&g_Ah0[(size_t)e * HD + c4]) = oh;
}

// attention logits + exp + segment-sum
__global__ void logit_kernel(const float* __restrict__ attnw,
                             const int* __restrict__ dst, int E) {
    int gid = blockIdx.x * blockDim.x + threadIdx.x;
    if (gid >= E * HHn) return;
    int e = gid >> 3, hh = gid & 7;
    const float* hp = &g_h[(size_t)e * HD + hh * 64];
    const float* ap = &attnw[hh * 64];
    float s = 0.f;
    #pragma unroll
    for (int k = 0; k < 16; ++k) {
        float4 hv = ld4(hp + k * 4);
        float4 av = ld4(ap + k * 4);
        s += hv.x * av.x + hv.y * av.y + hv.z * av.z + hv.w * av.w;
    }
    float a  = s > 0.f ? s : 0.01f * s;
    float ex = __expf(a);    // logits bounded; no max-shift needed (validated R5-R13)
    g_aexp[gid] = ex;
    atomicAdd(&g_asum[(size_t)dst[e] * HHn + hh], ex);
}

// alpha scale + scatter-sum into output
__global__ void finalize_kernel(const int* __restrict__ dst,
                                float* __restrict__ out, int E) {
    int i = blockIdx.x * blockDim.x + threadIdx.x;
    if (i >= E * (HD / 4)) return;
    int e = i >> 7, c4 = (i & 127) << 2;
    int hh = c4 >> 6;
    int dd = dst[e];
    float alpha = __fdividef(g_aexp[e * HHn + hh], g_asum[(size_t)dd * HHn + hh]);
    float4 v = ld4(&g_h[(size_t)e * HD + c4]);
    float* o = &out[(size_t)dd * HD + c4];
    atomicAdd(o + 0, v.x * alpha);
    atomicAdd(o + 1, v.y * alpha);
    atomicAdd(o + 2, v.z * alpha);
    atomicAdd(o + 3, v.w * alpha);
}

// ================= launcher =================
extern "C" void kernel_launch(void* const* d_in, const int* in_sizes, int n_in,
                              void* d_out, int out_size) {
    const float* feat  = (const float*)d_in[0];
    const float* Wih   = (const float*)d_in[1];
    const float* Whh   = (const float*)d_in[2];
    const float* bih   = (const float*)d_in[3];
    const float* bhh   = (const float*)d_in[4];
    const float* attnw = (const float*)d_in[5];
    const int* mp_idx  = (const int*)d_in[6];
    const int* dst     = (const int*)d_in[7];
    const int E     = in_sizes[7];
    const int nodes = in_sizes[0] / DF;
    float* out = (float*)d_out;
    const int nd8 = (out_size / HD) * HHn;

    float *pF, *pH;
    __half *pXh, *pXl, *pAh0, *pAh1, *pBhh, *pBih;
    cudaGetSymbolAddress((void**)&pF,   g_F);
    cudaGetSymbolAddress((void**)&pH,   g_h);
    cudaGetSymbolAddress((void**)&pXh,  g_Xh);
    cudaGetSymbolAddress((void**)&pXl,  g_Xl);
    cudaGetSymbolAddress((void**)&pAh0, g_Ah0);
    cudaGetSymbolAddress((void**)&pAh1, g_Ah1);
    cudaGetSymbolAddress((void**)&pBhh, g_Bhh);
    cudaGetSymbolAddress((void**)&pBih, g_Bih);

    cudaFuncSetAttribute(fgemm,        cudaFuncAttributeMaxDynamicSharedMemorySize, FSMEM);
    cudaFuncSetAttribute(step_gemm<1>, cudaFuncAttributeMaxDynamicSharedMemorySize, SSMEM);
    cudaFuncSetAttribute(step_gemm<2>, cudaFuncAttributeMaxDynamicSharedMemorySize, SSMEM);

    zero_kernel<<<2048, 256>>>(out, out_size, nd8);
    split_kernel<<<2048, 256>>>(feat, Whh, Wih, nodes);

    // F = x @ Wih^T + b_ih over nodes (3-term fp16, K'=192)
    dim3 gF(8, (nodes + 127) / 128);
    fgemm<<<gF, 256, FSMEM>>>(pXh, pXl, pBih, bih, pF, nodes);

    const int ew = (E * (HD / 4) + 255) / 256;
    step0_kernel<<<ew, 256>>>(mp_idx, bhh, E);

    dim3 gE(8, (E + 127) / 128);
    // step 1: A = fl16(h1); epilogue updates g_h in place + writes fl16 pong
    step_gemm<1><<<gE, 256, SSMEM>>>(pAh0, pBhh, bhh, mp_idx, pH, pAh1, E, 1);
    // step 2: A = fl16(h2); epilogue -> final fp32 h
    step_gemm<2><<<gE, 256, SSMEM>>>(pAh1, pBhh, bhh, mp_idx, pH, nullptr, E, 2);

    logit_kernel<<<(E * HHn + 255) / 256, 256>>>(attnw, dst, E);
    finalize_kernel<<<ew, 256>>>(dst, out, E);
}

// round 15
// speedup vs baseline: 1.0892x; 1.0892x over previous
#include <cuda_runtime.h>
#include <cuda_fp16.h>
#include <cstdint>

// ---------------- problem constants ----------------
#define DF    64
#define HHn   8
#define HD    512
#define G3    1536
#define NODES_MAX 100000
#define E_MAX     100000
#define ND_MAX    50000

// ---------------- device scratch ----------------
__device__ __half g_F[(size_t)NODES_MAX * G3];    // x@Wih^T + b_ih (fp16, halves traffic)
__device__ float g_h[(size_t)E_MAX * HD];         // fp32 hidden state (in-place)
__device__ __half g_Xh[(size_t)NODES_MAX * DF];   // feature splits (F-GEMM, 3-term)
__device__ __half g_Xl[(size_t)NODES_MAX * DF];
__device__ __half g_Ah0[(size_t)E_MAX * HD];      // fl16(h) ping
__device__ __half g_Ah1[(size_t)E_MAX * HD];      // fl16(h) pong
__device__ __half g_Bhh[(size_t)G3 * HD];         // fl16(Whh) (1.5 MB, L2-resident)
__device__ __half g_Bih[(size_t)G3 * (3 * DF)];   // Wih packed [Wh|Wl|Wh]
__device__ float g_aexp[(size_t)E_MAX * HHn];
__device__ float g_asum[(size_t)ND_MAX * HHn];

// ---------------- helpers ----------------
__device__ __forceinline__ uint32_t smem_u32(const void* p) {
    uint32_t a;
    asm("{ .reg .u64 t; cvta.to.shared.u64 t, %1; cvt.u32.u64 %0, t; }"
        : "=r"(a) : "l"(p));
    return a;
}
__device__ __forceinline__ void cp16(uint32_t s, const void* g) {
    asm volatile("cp.async.cg.shared.global [%0], [%1], 16;" :: "r"(s), "l"(g));
}
__device__ __forceinline__ void cp_commit() {
    asm volatile("cp.async.commit_group;" ::: "memory");
}
template<int N>
__device__ __forceinline__ void cp_wait() {
    asm volatile("cp.async.wait_group %0;" :: "n"(N) : "memory");
}
__device__ __forceinline__ void ldsm4(uint32_t& r0, uint32_t& r1, uint32_t& r2,
                                      uint32_t& r3, uint32_t addr) {
    asm volatile("ldmatrix.sync.aligned.m8n8.x4.shared.b16 {%0,%1,%2,%3}, [%4];"
                 : "=r"(r0), "=r"(r1), "=r"(r2), "=r"(r3) : "r"(addr));
}
// f32-accumulate HMMA (proven fastest variant, R13)
__device__ __forceinline__ void mma16816(float* c, const uint32_t* a,
                                         uint32_t b0, uint32_t b1) {
    asm volatile("mma.sync.aligned.m16n8k16.row.col.f32.f16.f16.f32 "
                 "{%0,%1,%2,%3}, {%4,%5,%6,%7}, {%8,%9}, {%0,%1,%2,%3};"
                 : "+f"(c[0]), "+f"(c[1]), "+f"(c[2]), "+f"(c[3])
                 : "r"(a[0]), "r"(a[1]), "r"(a[2]), "r"(a[3]), "r"(b0), "r"(b1));
}
__device__ __forceinline__ float2 ld2f(const float* p) { return *reinterpret_cast<const float2*>(p); }
__device__ __forceinline__ float4 ld4(const float* p)  { return *reinterpret_cast<const float4*>(p); }
__device__ __forceinline__ float2 ld2h(const __half* p) {
    return __half22float2(*reinterpret_cast<const __half2*>(p));
}
__device__ __forceinline__ float sigmf(float x) { return __fdividef(1.0f, 1.0f + __expf(-x)); }
__device__ __forceinline__ float tanhfast(float x) {
    return 1.0f - __fdividef(2.0f, __expf(2.0f * x) + 1.0f);
}
__device__ __forceinline__ float gru_one(float fr, float gr, float fz, float gz,
                                         float fn, float gn, float hp) {
    float r = sigmf(fr + gr);
    float z = sigmf(fz + gz);
    float n = tanhfast(fn + r * gn);
    return n + z * (hp - n);
}

// ================= step GEMM: f32-acc HMMA, single-sync pipeline =================
// 256 threads, 8 warps (4m x 2n). CTA tile: 128 rows x 64 cols x 3 gates. K'=512.
// A = fl16(h) [M,512]; B = fl16(Whh) [1536,512]. KTILE=64, T=8, depth-2 cp.async.
// Epilogue: fused GRU gates; fp32 hstate updated in place;
// MODE 1 additionally writes fl16(h_new) for the next step's A.
#define SHS    72                        // smem row stride (halves), 144 B
#define SABUF  (128 * SHS * 2)           // 18432 B
#define SBUF   (320 * SHS * 2)           // 46080 B
#define SSMEM  (2 * SBUF)                // 92160 B -> 2 CTAs/SM

template<int MODE>
__global__ void __launch_bounds__(256, 2)
step_gemm(const __half* __restrict__ Ain,
          const __half* __restrict__ Bp,
          const float* __restrict__ bias,
          const int* __restrict__ mp,
          float* __restrict__ hstate,
          __half* __restrict__ oA,
          int M, int t)
{
    extern __shared__ char sm[];
    const uint32_t sbase = smem_u32(sm);

    const int tid  = threadIdx.x;
    const int wid  = tid >> 5;
    const int lane = tid & 31;
    const int nb   = blockIdx.x * 64;
    const int mb   = blockIdx.y * 128;
    const int wq = wid >> 1;             // m quarter
    const int wn = wid & 1;              // n half (32 cols)

    float acc[3][2][4][4];
    #pragma unroll
    for (int g = 0; g < 3; ++g)
        #pragma unroll
        for (int i = 0; i < 2; ++i)
            #pragma unroll
            for (int j = 0; j < 4; ++j)
                #pragma unroll
                for (int c = 0; c < 4; ++c) acc[g][i][j][c] = 0.f;

    auto stage = [&](int kt) {
        const uint32_t ab = sbase + (kt & 1) * SBUF;
        const int kcol = kt * 64;
        #pragma unroll
        for (int it = 0; it < 10; ++it) {
            int i = tid + it * 256;      // 0..2559 (320 rows x 8 chunks)
            if (i < 1024) {
                int row = i >> 3, c = i & 7;
                int gr = mb + row; if (gr >= M) gr = M - 1;
                cp16(ab + (row * SHS + c * 8) * 2, &Ain[(size_t)gr * HD + kcol + c * 8]);
            } else {
                int j = i - 1024;
                int lr = j >> 3, c = j & 7;
                int grow = (lr >> 6) * 512 + nb + (lr & 63);
                cp16(ab + SABUF + (lr * SHS + c * 8) * 2,
                     &Bp[(size_t)grow * HD + kcol + c * 8]);
            }
        }
        cp_commit();
    };

    stage(0);
    for (int kt = 0; kt < 8; ++kt) {
        cp_wait<0>();                 // stage(kt) complete
        __syncthreads();              // all warps done reading buffer (kt-1)
        if (kt + 1 < 8) stage(kt + 1);

        const uint32_t ab = sbase + (kt & 1) * SBUF;
        const uint32_t bb = ab + SABUF;
        const int lr16 = lane & 15;
        const int koff = (lane >> 4) << 3;

        #pragma unroll
        for (int kk = 0; kk < 64; kk += 16) {
            uint32_t af[2][4];
            #pragma unroll
            for (int ma = 0; ma < 2; ++ma) {
                uint32_t a = ab + ((wq * 32 + ma * 16 + lr16) * SHS + kk + koff) * 2;
                ldsm4(af[ma][0], af[ma][1], af[ma][2], af[ma][3], a);
            }
            #pragma unroll
            for (int g = 0; g < 3; ++g) {
                #pragma unroll
                for (int np = 0; np < 2; ++np) {
                    uint32_t b0, b1, b2, b3;
                    uint32_t a = bb + ((g * 64 + wn * 32 + np * 16 + lr16) * SHS
                                       + kk + koff) * 2;
                    ldsm4(b0, b1, b2, b3, a);
                    #pragma unroll
                    for (int ma = 0; ma < 2; ++ma) {
                        mma16816(acc[g][ma][np * 2 + 0], af[ma], b0, b2);
                        mma16816(acc[g][ma][np * 2 + 1], af[ma], b1, b3);
                    }
                }
            }
        }
    }

    // ---- fused GRU epilogue ----
    const int gq  = lane >> 2;
    const int tig = lane & 3;
    #pragma unroll
    for (int ma = 0; ma < 2; ++ma) {
        #pragma unroll
        for (int p = 0; p < 2; ++p) {
            const int m = mb + wq * 32 + ma * 16 + gq + p * 8;
            if (m >= M) continue;
            const int node = mp[m * 3 + t];
            const __half* Fp = &g_F[(size_t)node * G3];
            #pragma unroll
            for (int na = 0; na < 4; ++na) {
                const int j = nb + wn * 32 + na * 8 + tig * 2;
                float vr0 = acc[0][ma][na][p * 2], vr1 = acc[0][ma][na][p * 2 + 1];
                float vz0 = acc[1][ma][na][p * 2], vz1 = acc[1][ma][na][p * 2 + 1];
                float vn0 = acc[2][ma][na][p * 2], vn1 = acc[2][ma][na][p * 2 + 1];
                float2 br = ld2f(&bias[j]);
                float2 bz = ld2f(&bias[512 + j]);
                float2 bn = ld2f(&bias[1024 + j]);
                float2 fr = ld2h(&Fp[j]);
                float2 fz = ld2h(&Fp[512 + j]);
                float2 fn = ld2h(&Fp[1024 + j]);
                float2 hp = ld2f(&hstate[(size_t)m * HD + j]);
                float h0 = gru_one(fr.x, vr0 + br.x, fz.x, vz0 + bz.x,
                                   fn.x, vn0 + bn.x, hp.x);
                float h1 = gru_one(fr.y, vr1 + br.y, fz.y, vz1 + bz.y,
                                   fn.y, vn1 + bn.y, hp.y);
                *reinterpret_cast<float2*>(&hstate[(size_t)m * HD + j]) =
                    make_float2(h0, h1);
                if (MODE == 1) {
                    *reinterpret_cast<__half2*>(&oA[(size_t)m * HD + j]) =
                        __floats2half2_rn(h0, h1);
                }
            }
        }
    }
}

// ================= F-GEMM (3-term fp16, f32-acc): F = x @ Wih^T + b_ih =================
#define FHS    72
#define FABUF  (128 * FHS * 2)
#define FBUFB  (320 * FHS * 2)
#define FSMEM  (2 * FBUFB)

__global__ void __launch_bounds__(256, 2)
fgemm(const __half* __restrict__ Xh,
      const __half* __restrict__ Xl,
      const __half* __restrict__ Bp,
      const float* __restrict__ bias,
      __half* __restrict__ outF, int M)
{
    extern __shared__ char sm[];
    const uint32_t sbase = smem_u32(sm);

    const int tid  = threadIdx.x;
    const int wid  = tid >> 5;
    const int lane = tid & 31;
    const int nb   = blockIdx.x * 64;
    const int mb   = blockIdx.y * 128;
    const int wq = wid >> 1;
    const int wn = wid & 1;

    float acc[3][2][4][4];
    #pragma unroll
    for (int g = 0; g < 3; ++g)
        #pragma unroll
        for (int i = 0; i < 2; ++i)
            #pragma unroll
            for (int j = 0; j < 4; ++j)
                #pragma unroll
                for (int c = 0; c < 4; ++c) acc[g][i][j][c] = 0.f;

    auto stage = [&](int kt) {
        const __half* As = (kt == 2) ? Xl : Xh;
        const uint32_t ab = sbase + (kt & 1) * FBUFB;
        #pragma unroll
        for (int it = 0; it < 10; ++it) {
            int i = tid + it * 256;
            if (i < 1024) {
                int row = i >> 3, c = i & 7;
                int gr = mb + row; if (gr >= M) gr = M - 1;
                cp16(ab + (row * FHS + c * 8) * 2, &As[(size_t)gr * DF + c * 8]);
            } else {
                int j = i - 1024;
                int lr = j >> 3, c = j & 7;
                int grow = (lr >> 6) * 512 + nb + (lr & 63);
                cp16(ab + FABUF + (lr * FHS + c * 8) * 2,
                     &Bp[(size_t)grow * 192 + kt * 64 + c * 8]);
            }
        }
        cp_commit();
    };

    stage(0);
    for (int kt = 0; kt < 3; ++kt) {
        cp_wait<0>();
        __syncthreads();
        if (kt + 1 < 3) stage(kt + 1);
        const uint32_t ab = sbase + (kt & 1) * FBUFB;
        const uint32_t bb = ab + FABUF;
        const int lr16 = lane & 15;
        const int koff = (lane >> 4) << 3;
        #pragma unroll
        for (int kk = 0; kk < 64; kk += 16) {
            uint32_t af[2][4];
            #pragma unroll
            for (int ma = 0; ma < 2; ++ma) {
                uint32_t a = ab + ((wq * 32 + ma * 16 + lr16) * FHS + kk + koff) * 2;
                ldsm4(af[ma][0], af[ma][1], af[ma][2], af[ma][3], a);
            }
            #pragma unroll
            for (int g = 0; g < 3; ++g) {
                #pragma unroll
                for (int np = 0; np < 2; ++np) {
                    uint32_t b0, b1, b2, b3;
                    uint32_t a = bb + ((g * 64 + wn * 32 + np * 16 + lr16) * FHS
                                       + kk + koff) * 2;
                    ldsm4(b0, b1, b2, b3, a);
                    #pragma unroll
                    for (int ma = 0; ma < 2; ++ma) {
                        mma16816(acc[g][ma][np * 2 + 0], af[ma], b0, b2);
                        mma16816(acc[g][ma][np * 2 + 1], af[ma], b1, b3);
                    }
                }
            }
        }
    }

    const int gq  = lane >> 2;
    const int tig = lane & 3;
    #pragma unroll
    for (int ma = 0; ma < 2; ++ma) {
        #pragma unroll
        for (int p = 0; p < 2; ++p) {
            const int m = mb + wq * 32 + ma * 16 + gq + p * 8;
            if (m >= M) continue;
            #pragma unroll
            for (int na = 0; na < 4; ++na) {
                const int j = nb + wn * 32 + na * 8 + tig * 2;
                float2 br = ld2f(&bias[j]);
                float2 bz = ld2f(&bias[512 + j]);
                float2 bn = ld2f(&bias[1024 + j]);
                *reinterpret_cast<__half2*>(&outF[(size_t)m * G3 + j]) =
                    __floats2half2_rn(acc[0][ma][na][p*2] + br.x, acc[0][ma][na][p*2+1] + br.y);
                *reinterpret_cast<__half2*>(&outF[(size_t)m * G3 + 512 + j]) =
                    __floats2half2_rn(acc[1][ma][na][p*2] + bz.x, acc[1][ma][na][p*2+1] + bz.y);
                *reinterpret_cast<__half2*>(&outF[(size_t)m * G3 + 1024 + j]) =
                    __floats2half2_rn(acc[2][ma][na][p*2] + bn.x, acc[2][ma][na][p*2+1] + bn.y);
            }
        }
    }
}

// ================= elementwise kernels =================
__global__ void zero_kernel(float* __restrict__ out, int nOut, int nSum) {
    int stride = gridDim.x * blockDim.x;
    int i0 = blockIdx.x * blockDim.x + threadIdx.x;
    for (int i = i0; i < nOut; i += stride) out[i] = 0.0f;
    for (int i = i0; i < nSum; i += stride) g_asum[i] = 0.0f;
}

__global__ void split_kernel(const float* __restrict__ feat,
                             const float* __restrict__ Whh,
                             const float* __restrict__ Wih, int nodes) {
    int stride = gridDim.x * blockDim.x;
    int i0 = blockIdx.x * blockDim.x + threadIdx.x;
    for (int i = i0; i < nodes * DF; i += stride) {
        __half h = __float2half_rn(feat[i]);
        __half l = __float2half_rn(feat[i] - __half2float(h));
        g_Xh[i] = h;
        g_Xl[i] = l;
    }
    for (int i = i0; i < G3 * HD; i += stride)
        g_Bhh[i] = __float2half_rn(Whh[i]);
    for (int i = i0; i < G3 * DF; i += stride) {
        int n = i >> 6, k = i & 63;
        __half h = __float2half_rn(Wih[i]);
        __half l = __float2half_rn(Wih[i] - __half2float(h));
        size_t b = (size_t)n * (3 * DF);
        g_Bih[b + k]       = h;
        g_Bih[b + 64 + k]  = l;
        g_Bih[b + 128 + k] = h;
    }
}

// step 0: h1 = gru(F[node0], b_hh, h=0); write fp32 g_h + fp16 g_Ah0
__global__ void step0_kernel(const int* __restrict__ mp,
                             const float* __restrict__ bhh, int E) {
    int i = blockIdx.x * blockDim.x + threadIdx.x;
    if (i >= E * (HD / 4)) return;
    int e = i >> 7, c4 = (i & 127) << 2;
    int node = mp[e * 3];
    const __half* Fp = &g_F[(size_t)node * G3];
    float2 fr0 = ld2h(Fp + c4),        fr1 = ld2h(Fp + c4 + 2);
    float2 fz0 = ld2h(Fp + 512 + c4),  fz1 = ld2h(Fp + 512 + c4 + 2);
    float2 fn0 = ld2h(Fp + 1024 + c4), fn1 = ld2h(Fp + 1024 + c4 + 2);
    float4 br = ld4(bhh + c4), bz = ld4(bhh + 512 + c4), bn = ld4(bhh + 1024 + c4);
    float h0 = gru_one(fr0.x, br.x, fz0.x, bz.x, fn0.x, bn.x, 0.f);
    float h1 = gru_one(fr0.y, br.y, fz0.y, bz.y, fn0.y, bn.y, 0.f);
    float h2 = gru_one(fr1.x, br.z, fz1.x, bz.z, fn1.x, bn.z, 0.f);
    float h3 = gru_one(fr1.y, br.w, fz1.y, bz.w, fn1.y, bn.w, 0.f);
    *reinterpret_cast<float4*>(&g_h[(size_t)e * HD + c4]) = make_float4(h0, h1, h2, h3);
    __half2 oh0 = __floats2half2_rn(h0, h1);
    __half2 oh1 = __floats2half2_rn(h2, h3);
    *reinterpret_cast<__half2*>(&g_Ah0[(size_t)e * HD + c4])     = oh0;
    *reinterpret_cast<__half2*>(&g_Ah0[(size_t)e * HD + c4 + 2]) = oh1;
}

// attention logits + exp + segment-sum
__global__ void logit_kernel(const float* __restrict__ attnw,
                             const int* __restrict__ dst, int E) {
    int gid = blockIdx.x * blockDim.x + threadIdx.x;
    if (gid >= E * HHn) return;
    int e = gid >> 3, hh = gid & 7;
    const float* hp = &g_h[(size_t)e * HD + hh * 64];
    const float* ap = &attnw[hh * 64];
    float s = 0.f;
    #pragma unroll
    for (int k = 0; k < 16; ++k) {
        float4 hv = ld4(hp + k * 4);
        float4 av = ld4(ap + k * 4);
        s += hv.x * av.x + hv.y * av.y + hv.z * av.z + hv.w * av.w;
    }
    float a  = s > 0.f ? s : 0.01f * s;
    float ex = __expf(a);    // logits bounded; no max-shift needed (validated R5-R14)
    g_aexp[gid] = ex;
    atomicAdd(&g_asum[(size_t)dst[e] * HHn + hh], ex);
}

// alpha scale + scatter-sum into output
__global__ void finalize_kernel(const int* __restrict__ dst,
                                float* __restrict__ out, int E) {
    int i = blockIdx.x * blockDim.x + threadIdx.x;
    if (i >= E * (HD / 4)) return;
    int e = i >> 7, c4 = (i & 127) << 2;
    int hh = c4 >> 6;
    int dd = dst[e];
    float alpha = __fdividef(g_aexp[e * HHn + hh], g_asum[(size_t)dd * HHn + hh]);
    float4 v = ld4(&g_h[(size_t)e * HD + c4]);
    float* o = &out[(size_t)dd * HD + c4];
    atomicAdd(o + 0, v.x * alpha);
    atomicAdd(o + 1, v.y * alpha);
    atomicAdd(o + 2, v.z * alpha);
    atomicAdd(o + 3, v.w * alpha);
}

// ================= launcher =================
extern "C" void kernel_launch(void* const* d_in, const int* in_sizes, int n_in,
                              void* d_out, int out_size) {
    const float* feat  = (const float*)d_in[0];
    const float* Wih   = (const float*)d_in[1];
    const float* Whh   = (const float*)d_in[2];
    const float* bih   = (const float*)d_in[3];
    const float* bhh   = (const float*)d_in[4];
    const float* attnw = (const float*)d_in[5];
    const int* mp_idx  = (const int*)d_in[6];
    const int* dst     = (const int*)d_in[7];
    const int E     = in_sizes[7];
    const int nodes = in_sizes[0] / DF;
    float* out = (float*)d_out;
    const int nd8 = (out_size / HD) * HHn;

    float* pH;
    __half *pF, *pXh, *pXl, *pAh0, *pAh1, *pBhh, *pBih;
    cudaGetSymbolAddress((void**)&pF,   g_F);
    cudaGetSymbolAddress((void**)&pH,   g_h);
    cudaGetSymbolAddress((void**)&pXh,  g_Xh);
    cudaGetSymbolAddress((void**)&pXl,  g_Xl);
    cudaGetSymbolAddress((void**)&pAh0, g_Ah0);
    cudaGetSymbolAddress((void**)&pAh1, g_Ah1);
    cudaGetSymbolAddress((void**)&pBhh, g_Bhh);
    cudaGetSymbolAddress((void**)&pBih, g_Bih);

    cudaFuncSetAttribute(fgemm,        cudaFuncAttributeMaxDynamicSharedMemorySize, FSMEM);
    cudaFuncSetAttribute(step_gemm<1>, cudaFuncAttributeMaxDynamicSharedMemorySize, SSMEM);
    cudaFuncSetAttribute(step_gemm<2>, cudaFuncAttributeMaxDynamicSharedMemorySize, SSMEM);

    zero_kernel<<<2048, 256>>>(out, out_size, nd8);
    split_kernel<<<2048, 256>>>(feat, Whh, Wih, nodes);

    // F = x @ Wih^T + b_ih over nodes (3-term fp16, K'=192), F stored fp16
    dim3 gF(8, (nodes + 127) / 128);
    fgemm<<<gF, 256, FSMEM>>>(pXh, pXl, pBih, bih, pF, nodes);

    const int ew = (E * (HD / 4) + 255) / 256;
    step0_kernel<<<ew, 256>>>(mp_idx, bhh, E);

    dim3 gE(8, (E + 127) / 128);
    // step 1: A = fl16(h1); epilogue updates g_h in place + writes fl16 pong
    step_gemm<1><<<gE, 256, SSMEM>>>(pAh0, pBhh, bhh, mp_idx, pH, pAh1, E, 1);
    // step 2: A = fl16(h2); epilogue -> final fp32 h
    step_gemm<2><<<gE, 256, SSMEM>>>(pAh1, pBhh, bhh, mp_idx, pH, nullptr, E, 2);

    logit_kernel<<<(E * HHn + 255) / 256, 256>>>(attnw, dst, E);
    finalize_kernel<<<ew, 256>>>(dst, out, E);
}

// round 16
// speedup vs baseline: 1.5241x; 1.3993x over previous
#include <cuda_runtime.h>
#include <cuda_fp16.h>
#include <cstdint>

// ---------------- problem constants ----------------
#define DF    64
#define HHn   8
#define HD    512
#define G3    1536
#define NODES_MAX 100000
#define E_MAX     100000
#define ND_MAX    50000

// ---------------- device scratch ----------------
__device__ __half g_F[(size_t)NODES_MAX * G3];    // x@Wih^T + b_ih (fp16)
__device__ float g_h[(size_t)E_MAX * HD];         // fp32 hidden (steps 0,1 carry)
__device__ __half g_Xh[(size_t)NODES_MAX * DF];   // feature splits
__device__ __half g_Xl[(size_t)NODES_MAX * DF];
__device__ __half g_Ah0[(size_t)E_MAX * HD];      // fl16(h1); later reused as fp16 eft
__device__ __half g_Ah1[(size_t)E_MAX * HD];      // fl16(h2)
__device__ __half g_Bhh[(size_t)G3 * HD];         // fl16(Whh)
__device__ __half g_Bih[(size_t)G3 * 128];        // Wih packed [Wh|Wh] (2-term)
__device__ float g_aexp[(size_t)E_MAX * HHn];
__device__ float g_asum[(size_t)ND_MAX * HHn];

// ---------------- helpers ----------------
__device__ __forceinline__ uint32_t smem_u32(const void* p) {
    uint32_t a;
    asm("{ .reg .u64 t; cvta.to.shared.u64 t, %1; cvt.u32.u64 %0, t; }"
        : "=r"(a) : "l"(p));
    return a;
}
__device__ __forceinline__ void cp16(uint32_t s, const void* g) {
    asm volatile("cp.async.cg.shared.global [%0], [%1], 16;" :: "r"(s), "l"(g));
}
__device__ __forceinline__ void cp_commit() {
    asm volatile("cp.async.commit_group;" ::: "memory");
}
template<int N>
__device__ __forceinline__ void cp_wait() {
    asm volatile("cp.async.wait_group %0;" :: "n"(N) : "memory");
}
__device__ __forceinline__ void ldsm4(uint32_t& r0, uint32_t& r1, uint32_t& r2,
                                      uint32_t& r3, uint32_t addr) {
    asm volatile("ldmatrix.sync.aligned.m8n8.x4.shared.b16 {%0,%1,%2,%3}, [%4];"
                 : "=r"(r0), "=r"(r1), "=r"(r2), "=r"(r3) : "r"(addr));
}
// f32-accumulate HMMA (proven fastest variant, R13)
__device__ __forceinline__ void mma16816(float* c, const uint32_t* a,
                                         uint32_t b0, uint32_t b1) {
    asm volatile("mma.sync.aligned.m16n8k16.row.col.f32.f16.f16.f32 "
                 "{%0,%1,%2,%3}, {%4,%5,%6,%7}, {%8,%9}, {%0,%1,%2,%3};"
                 : "+f"(c[0]), "+f"(c[1]), "+f"(c[2]), "+f"(c[3])
                 : "r"(a[0]), "r"(a[1]), "r"(a[2]), "r"(a[3]), "r"(b0), "r"(b1));
}
__device__ __forceinline__ float2 ld2f(const float* p) { return *reinterpret_cast<const float2*>(p); }
__device__ __forceinline__ float4 ld4(const float* p)  { return *reinterpret_cast<const float4*>(p); }
__device__ __forceinline__ float2 ld2h(const __half* p) {
    return __half22float2(*reinterpret_cast<const __half2*>(p));
}
__device__ __forceinline__ float sigmf(float x) { return __fdividef(1.0f, 1.0f + __expf(-x)); }
__device__ __forceinline__ float tanhfast(float x) {
    return 1.0f - __fdividef(2.0f, __expf(2.0f * x) + 1.0f);
}
__device__ __forceinline__ float gru_one(float fr, float gr, float fz, float gz,
                                         float fn, float gn, float hp) {
    float r = sigmf(fr + gr);
    float z = sigmf(fz + gz);
    float n = tanhfast(fn + r * gn);
    return n + z * (hp - n);
}

// ================= step GEMM: f32-acc HMMA, single-sync pipeline =================
// 256 threads, 8 warps (4m x 2n). CTA tile: 128 rows x 64 cols x 3 gates. K'=512.
// MODE 1: h2 -> fp32 g_h (in place) + fl16 pong.
// MODE 2: final h -> fp16 eft (oA) + FUSED attention logit (this CTA's 64 cols
//         are exactly head blockIdx.x; per-row dot via smem reduction).
#define SHS    72                        // smem row stride (halves), 144 B
#define SABUF  (128 * SHS * 2)           // 18432 B
#define SBUF   (320 * SHS * 2)           // 46080 B
#define SSMEM  (2 * SBUF)                // 92160 B -> 2 CTAs/SM

template<int MODE>
__global__ void __launch_bounds__(256, 2)
step_gemm(const __half* __restrict__ Ain,
          const __half* __restrict__ Bp,
          const float* __restrict__ bias,
          const int* __restrict__ mp,
          const int* __restrict__ dst,
          const float* __restrict__ attnw,
          float* __restrict__ hstate,
          __half* __restrict__ oA,
          int M, int t)
{
    extern __shared__ char sm[];
    const uint32_t sbase = smem_u32(sm);

    const int tid  = threadIdx.x;
    const int wid  = tid >> 5;
    const int lane = tid & 31;
    const int nb   = blockIdx.x * 64;
    const int mb   = blockIdx.y * 128;
    const int wq = wid >> 1;             // m quarter
    const int wn = wid & 1;              // n half (32 cols)

    float acc[3][2][4][4];
    #pragma unroll
    for (int g = 0; g < 3; ++g)
        #pragma unroll
        for (int i = 0; i < 2; ++i)
            #pragma unroll
            for (int j = 0; j < 4; ++j)
                #pragma unroll
                for (int c = 0; c < 4; ++c) acc[g][i][j][c] = 0.f;

    auto stage = [&](int kt) {
        const uint32_t ab = sbase + (kt & 1) * SBUF;
        const int kcol = kt * 64;
        #pragma unroll
        for (int it = 0; it < 10; ++it) {
            int i = tid + it * 256;      // 0..2559 (320 rows x 8 chunks)
            if (i < 1024) {
                int row = i >> 3, c = i & 7;
                int gr = mb + row; if (gr >= M) gr = M - 1;
                cp16(ab + (row * SHS + c * 8) * 2, &Ain[(size_t)gr * HD + kcol + c * 8]);
            } else {
                int j = i - 1024;
                int lr = j >> 3, c = j & 7;
                int grow = (lr >> 6) * 512 + nb + (lr & 63);
                cp16(ab + SABUF + (lr * SHS + c * 8) * 2,
                     &Bp[(size_t)grow * HD + kcol + c * 8]);
            }
        }
        cp_commit();
    };

    stage(0);
    for (int kt = 0; kt < 8; ++kt) {
        cp_wait<0>();
        __syncthreads();
        if (kt + 1 < 8) stage(kt + 1);

        const uint32_t ab = sbase + (kt & 1) * SBUF;
        const uint32_t bb = ab + SABUF;
        const int lr16 = lane & 15;
        const int koff = (lane >> 4) << 3;

        #pragma unroll
        for (int kk = 0; kk < 64; kk += 16) {
            uint32_t af[2][4];
            #pragma unroll
            for (int ma = 0; ma < 2; ++ma) {
                uint32_t a = ab + ((wq * 32 + ma * 16 + lr16) * SHS + kk + koff) * 2;
                ldsm4(af[ma][0], af[ma][1], af[ma][2], af[ma][3], a);
            }
            #pragma unroll
            for (int g = 0; g < 3; ++g) {
                #pragma unroll
                for (int np = 0; np < 2; ++np) {
                    uint32_t b0, b1, b2, b3;
                    uint32_t a = bb + ((g * 64 + wn * 32 + np * 16 + lr16) * SHS
                                       + kk + koff) * 2;
                    ldsm4(b0, b1, b2, b3, a);
                    #pragma unroll
                    for (int ma = 0; ma < 2; ++ma) {
                        mma16816(acc[g][ma][np * 2 + 0], af[ma], b0, b2);
                        mma16816(acc[g][ma][np * 2 + 1], af[ma], b1, b3);
                    }
                }
            }
        }
    }

    // ---- fused GRU epilogue ----
    float* s_logit = reinterpret_cast<float*>(sm);   // buffer0 region, safe post-loop
    if (MODE == 2) {
        if (tid < 128) s_logit[tid] = 0.f;
        __syncthreads();
    }

    const int gq  = lane >> 2;
    const int tig = lane & 3;
    #pragma unroll
    for (int ma = 0; ma < 2; ++ma) {
        #pragma unroll
        for (int p = 0; p < 2; ++p) {
            const int mrow = wq * 32 + ma * 16 + gq + p * 8;
            const int m = mb + mrow;
            if (m >= M) continue;
            const int node = mp[m * 3 + t];
            const __half* Fp = &g_F[(size_t)node * G3];
            float part = 0.f;
            #pragma unroll
            for (int na = 0; na < 4; ++na) {
                const int j = nb + wn * 32 + na * 8 + tig * 2;
                float vr0 = acc[0][ma][na][p * 2], vr1 = acc[0][ma][na][p * 2 + 1];
                float vz0 = acc[1][ma][na][p * 2], vz1 = acc[1][ma][na][p * 2 + 1];
                float vn0 = acc[2][ma][na][p * 2], vn1 = acc[2][ma][na][p * 2 + 1];
                float2 br = ld2f(&bias[j]);
                float2 bz = ld2f(&bias[512 + j]);
                float2 bn = ld2f(&bias[1024 + j]);
                float2 fr = ld2h(&Fp[j]);
                float2 fz = ld2h(&Fp[512 + j]);
                float2 fn = ld2h(&Fp[1024 + j]);
                float2 hp = ld2f(&hstate[(size_t)m * HD + j]);
                float h0 = gru_one(fr.x, vr0 + br.x, fz.x, vz0 + bz.x,
                                   fn.x, vn0 + bn.x, hp.x);
                float h1 = gru_one(fr.y, vr1 + br.y, fz.y, vz1 + bz.y,
                                   fn.y, vn1 + bn.y, hp.y);
                if (MODE == 1) {
                    *reinterpret_cast<float2*>(&hstate[(size_t)m * HD + j]) =
                        make_float2(h0, h1);
                    *reinterpret_cast<__half2*>(&oA[(size_t)m * HD + j]) =
                        __floats2half2_rn(h0, h1);
                } else {
                    *reinterpret_cast<__half2*>(&oA[(size_t)m * HD + j]) =
                        __floats2half2_rn(h0, h1);
                    float2 aw = ld2f(&attnw[j]);     // attnw flat [512] == hidden col
                    part += h0 * aw.x + h1 * aw.y;
                }
            }
            if (MODE == 2) atomicAdd(&s_logit[mrow], part);
        }
    }

    if (MODE == 2) {
        __syncthreads();
        if (tid < 128) {
            int e = mb + tid;
            if (e < M) {
                const int hh = nb >> 6;           // this CTA's head
                float a  = s_logit[tid];
                a = a > 0.f ? a : 0.01f * a;      // leaky relu
                float ex = __expf(a);             // logits bounded (validated R5-R15)
                g_aexp[(size_t)e * HHn + hh] = ex;
                atomicAdd(&g_asum[(size_t)dst[e] * HHn + hh], ex);
            }
        }
    }
}

// ================= F-GEMM (2-term fp16): F = fl16(x) @ fl16(Wih)^T + b_ih =================
// A' = [Xh | Xl], B' = [Wh | Wh]; K'=128, 2 tiles of 64.
#define FHS    72
#define FABUF  (128 * FHS * 2)
#define FBUFB  (320 * FHS * 2)
#define FSMEM  (2 * FBUFB)

__global__ void __launch_bounds__(256, 2)
fgemm(const __half* __restrict__ Xh,
      const __half* __restrict__ Xl,
      const __half* __restrict__ Bp,
      const float* __restrict__ bias,
      __half* __restrict__ outF, int M)
{
    extern __shared__ char sm[];
    const uint32_t sbase = smem_u32(sm);

    const int tid  = threadIdx.x;
    const int wid  = tid >> 5;
    const int lane = tid & 31;
    const int nb   = blockIdx.x * 64;
    const int mb   = blockIdx.y * 128;
    const int wq = wid >> 1;
    const int wn = wid & 1;

    float acc[3][2][4][4];
    #pragma unroll
    for (int g = 0; g < 3; ++g)
        #pragma unroll
        for (int i = 0; i < 2; ++i)
            #pragma unroll
            for (int j = 0; j < 4; ++j)
                #pragma unroll
                for (int c = 0; c < 4; ++c) acc[g][i][j][c] = 0.f;

    auto stage = [&](int kt) {
        const __half* As = (kt == 1) ? Xl : Xh;
        const uint32_t ab = sbase + (kt & 1) * FBUFB;
        #pragma unroll
        for (int it = 0; it < 10; ++it) {
            int i = tid + it * 256;
            if (i < 1024) {
                int row = i >> 3, c = i & 7;
                int gr = mb + row; if (gr >= M) gr = M - 1;
                cp16(ab + (row * FHS + c * 8) * 2, &As[(size_t)gr * DF + c * 8]);
            } else {
                int j = i - 1024;
                int lr = j >> 3, c = j & 7;
                int grow = (lr >> 6) * 512 + nb + (lr & 63);
                cp16(ab + FABUF + (lr * FHS + c * 8) * 2,
                     &Bp[(size_t)grow * 128 + kt * 64 + c * 8]);
            }
        }
        cp_commit();
    };

    stage(0);
    for (int kt = 0; kt < 2; ++kt) {
        cp_wait<0>();
        __syncthreads();
        if (kt + 1 < 2) stage(kt + 1);
        const uint32_t ab = sbase + (kt & 1) * FBUFB;
        const uint32_t bb = ab + FABUF;
        const int lr16 = lane & 15;
        const int koff = (lane >> 4) << 3;
        #pragma unroll
        for (int kk = 0; kk < 64; kk += 16) {
            uint32_t af[2][4];
            #pragma unroll
            for (int ma = 0; ma < 2; ++ma) {
                uint32_t a = ab + ((wq * 32 + ma * 16 + lr16) * FHS + kk + koff) * 2;
                ldsm4(af[ma][0], af[ma][1], af[ma][2], af[ma][3], a);
            }
            #pragma unroll
            for (int g = 0; g < 3; ++g) {
                #pragma unroll
                for (int np = 0; np < 2; ++np) {
                    uint32_t b0, b1, b2, b3;
                    uint32_t a = bb + ((g * 64 + wn * 32 + np * 16 + lr16) * FHS
                                       + kk + koff) * 2;
                    ldsm4(b0, b1, b2, b3, a);
                    #pragma unroll
                    for (int ma = 0; ma < 2; ++ma) {
                        mma16816(acc[g][ma][np * 2 + 0], af[ma], b0, b2);
                        mma16816(acc[g][ma][np * 2 + 1], af[ma], b1, b3);
                    }
                }
            }
        }
    }

    const int gq  = lane >> 2;
    const int tig = lane & 3;
    #pragma unroll
    for (int ma = 0; ma < 2; ++ma) {
        #pragma unroll
        for (int p = 0; p < 2; ++p) {
            const int m = mb + wq * 32 + ma * 16 + gq + p * 8;
            if (m >= M) continue;
            #pragma unroll
            for (int na = 0; na < 4; ++na) {
                const int j = nb + wn * 32 + na * 8 + tig * 2;
                float2 br = ld2f(&bias[j]);
                float2 bz = ld2f(&bias[512 + j]);
                float2 bn = ld2f(&bias[1024 + j]);
                *reinterpret_cast<__half2*>(&outF[(size_t)m * G3 + j]) =
                    __floats2half2_rn(acc[0][ma][na][p*2] + br.x, acc[0][ma][na][p*2+1] + br.y);
                *reinterpret_cast<__half2*>(&outF[(size_t)m * G3 + 512 + j]) =
                    __floats2half2_rn(acc[1][ma][na][p*2] + bz.x, acc[1][ma][na][p*2+1] + bz.y);
                *reinterpret_cast<__half2*>(&outF[(size_t)m * G3 + 1024 + j]) =
                    __floats2half2_rn(acc[2][ma][na][p*2] + bn.x, acc[2][ma][na][p*2+1] + bn.y);
            }
        }
    }
}

// ================= elementwise kernels =================
__global__ void zero_kernel(float* __restrict__ out, int nOut, int nSum) {
    int stride = gridDim.x * blockDim.x;
    int i0 = blockIdx.x * blockDim.x + threadIdx.x;
    for (int i = i0; i < nOut; i += stride) out[i] = 0.0f;
    for (int i = i0; i < nSum; i += stride) g_asum[i] = 0.0f;
}

__global__ void split_kernel(const float* __restrict__ feat,
                             const float* __restrict__ Whh,
                             const float* __restrict__ Wih, int nodes) {
    int stride = gridDim.x * blockDim.x;
    int i0 = blockIdx.x * blockDim.x + threadIdx.x;
    for (int i = i0; i < nodes * DF; i += stride) {
        __half h = __float2half_rn(feat[i]);
        __half l = __float2half_rn(feat[i] - __half2float(h));
        g_Xh[i] = h;
        g_Xl[i] = l;
    }
    for (int i = i0; i < G3 * HD; i += stride)
        g_Bhh[i] = __float2half_rn(Whh[i]);
    for (int i = i0; i < G3 * DF; i += stride) {
        int n = i >> 6, k = i & 63;
        __half h = __float2half_rn(Wih[i]);
        size_t b = (size_t)n * 128;
        g_Bih[b + k]      = h;
        g_Bih[b + 64 + k] = h;
    }
}

// step 0: h1 = gru(F[node0], b_hh, h=0); write fp32 g_h + fp16 g_Ah0
__global__ void step0_kernel(const int* __restrict__ mp,
                             const float* __restrict__ bhh, int E) {
    int i = blockIdx.x * blockDim.x + threadIdx.x;
    if (i >= E * (HD / 4)) return;
    int e = i >> 7, c4 = (i & 127) << 2;
    int node = mp[e * 3];
    const __half* Fp = &g_F[(size_t)node * G3];
    float2 fr0 = ld2h(Fp + c4),        fr1 = ld2h(Fp + c4 + 2);
    float2 fz0 = ld2h(Fp + 512 + c4),  fz1 = ld2h(Fp + 512 + c4 + 2);
    float2 fn0 = ld2h(Fp + 1024 + c4), fn1 = ld2h(Fp + 1024 + c4 + 2);
    float4 br = ld4(bhh + c4), bz = ld4(bhh + 512 + c4), bn = ld4(bhh + 1024 + c4);
    float h0 = gru_one(fr0.x, br.x, fz0.x, bz.x, fn0.x, bn.x, 0.f);
    float h1 = gru_one(fr0.y, br.y, fz0.y, bz.y, fn0.y, bn.y, 0.f);
    float h2 = gru_one(fr1.x, br.z, fz1.x, bz.z, fn1.x, bn.z, 0.f);
    float h3 = gru_one(fr1.y, br.w, fz1.y, bz.w, fn1.y, bn.w, 0.f);
    *reinterpret_cast<float4*>(&g_h[(size_t)e * HD + c4]) = make_float4(h0, h1, h2, h3);
    *reinterpret_cast<__half2*>(&g_Ah0[(size_t)e * HD + c4])     = __floats2half2_rn(h0, h1);
    *reinterpret_cast<__half2*>(&g_Ah0[(size_t)e * HD + c4 + 2]) = __floats2half2_rn(h2, h3);
}

// alpha scale + scatter-sum into output (eft fp16)
__global__ void finalize_kernel(const int* __restrict__ dst,
                                const __half* __restrict__ eft,
                                float* __restrict__ out, int E) {
    int i = blockIdx.x * blockDim.x + threadIdx.x;
    if (i >= E * (HD / 4)) return;
    int e = i >> 7, c4 = (i & 127) << 2;
    int hh = c4 >> 6;
    int dd = dst[e];
    float alpha = __fdividef(g_aexp[(size_t)e * HHn + hh],
                             g_asum[(size_t)dd * HHn + hh]);
    float2 v0 = ld2h(&eft[(size_t)e * HD + c4]);
    float2 v1 = ld2h(&eft[(size_t)e * HD + c4 + 2]);
    float* o = &out[(size_t)dd * HD + c4];
    atomicAdd(o + 0, v0.x * alpha);
    atomicAdd(o + 1, v0.y * alpha);
    atomicAdd(o + 2, v1.x * alpha);
    atomicAdd(o + 3, v1.y * alpha);
}

// ================= launcher =================
extern "C" void kernel_launch(void* const* d_in, const int* in_sizes, int n_in,
                              void* d_out, int out_size) {
    const float* feat  = (const float*)d_in[0];
    const float* Wih   = (const float*)d_in[1];
    const float* Whh   = (const float*)d_in[2];
    const float* bih   = (const float*)d_in[3];
    const float* bhh   = (const float*)d_in[4];
    const float* attnw = (const float*)d_in[5];
    const int* mp_idx  = (const int*)d_in[6];
    const int* dst     = (const int*)d_in[7];
    const int E     = in_sizes[7];
    const int nodes = in_sizes[0] / DF;
    float* out = (float*)d_out;
    const int nd8 = (out_size / HD) * HHn;

    float* pH;
    __half *pF, *pXh, *pXl, *pAh0, *pAh1, *pBhh, *pBih;
    cudaGetSymbolAddress((void**)&pF,   g_F);
    cudaGetSymbolAddress((void**)&pH,   g_h);
    cudaGetSymbolAddress((void**)&pXh,  g_Xh);
    cudaGetSymbolAddress((void**)&pXl,  g_Xl);
    cudaGetSymbolAddress((void**)&pAh0, g_Ah0);
    cudaGetSymbolAddress((void**)&pAh1, g_Ah1);
    cudaGetSymbolAddress((void**)&pBhh, g_Bhh);
    cudaGetSymbolAddress((void**)&pBih, g_Bih);

    cudaFuncSetAttribute(fgemm,        cudaFuncAttributeMaxDynamicSharedMemorySize, FSMEM);
    cudaFuncSetAttribute(step_gemm<1>, cudaFuncAttributeMaxDynamicSharedMemorySize, SSMEM);
    cudaFuncSetAttribute(step_gemm<2>, cudaFuncAttributeMaxDynamicSharedMemorySize, SSMEM);

    zero_kernel<<<2048, 256>>>(out, out_size, nd8);
    split_kernel<<<2048, 256>>>(feat, Whh, Wih, nodes);

    // F = fl16(x) @ fl16(Wih)^T + b_ih over nodes (2-term, K'=128)
    dim3 gF(8, (nodes + 127) / 128);
    fgemm<<<gF, 256, FSMEM>>>(pXh, pXl, pBih, bih, pF, nodes);

    const int ew = (E * (HD / 4) + 255) / 256;
    step0_kernel<<<ew, 256>>>(mp_idx, bhh, E);

    dim3 gE(8, (E + 127) / 128);
    // step 1: gh = fl16(h1)@Whh^T + b_hh; updates g_h fp32 + fl16 pong
    step_gemm<1><<<gE, 256, SSMEM>>>(pAh0, pBhh, bhh, mp_idx, dst, attnw,
                                     pH, pAh1, E, 1);
    // step 2: final h -> fp16 eft (reuse Ah0) + fused logits/segment-sums
    step_gemm<2><<<gE, 256, SSMEM>>>(pAh1, pBhh, bhh, mp_idx, dst, attnw,
                                     pH, pAh0, E, 2);

    finalize_kernel<<<ew, 256>>>(dst, pAh0, out, E);
}

// round 17
// speedup vs baseline: 1.5800x; 1.0367x over previous
#include <cuda_runtime.h>
#include <cuda_fp16.h>
#include <cstdint>

// ---------------- problem constants ----------------
#define DF    64
#define HHn   8
#define HD    512
#define G3    1536
#define NODES_MAX 100000
#define E_MAX     100000
#define ND_MAX    50000

// ---------------- device scratch ----------------
__device__ __half g_F[(size_t)NODES_MAX * G3];    // x@Wih^T + b_ih (fp16)
__device__ __half g_Xh[(size_t)NODES_MAX * DF];   // feature splits
__device__ __half g_Xl[(size_t)NODES_MAX * DF];
__device__ __half g_Ah0[(size_t)E_MAX * HD];      // fl16(h1); later reused as fp16 eft
__device__ __half g_Ah1[(size_t)E_MAX * HD];      // fl16(h2)
__device__ __half g_Bhh[(size_t)G3 * HD];         // fl16(Whh)
__device__ __half g_Bih[(size_t)G3 * 128];        // Wih packed [Wh|Wh] (2-term)
__device__ float g_aexp[(size_t)E_MAX * HHn];
__device__ float g_asum[(size_t)ND_MAX * HHn];

// ---------------- helpers ----------------
__device__ __forceinline__ uint32_t smem_u32(const void* p) {
    uint32_t a;
    asm("{ .reg .u64 t; cvta.to.shared.u64 t, %1; cvt.u32.u64 %0, t; }"
        : "=r"(a) : "l"(p));
    return a;
}
__device__ __forceinline__ void cp16(uint32_t s, const void* g) {
    asm volatile("cp.async.cg.shared.global [%0], [%1], 16;" :: "r"(s), "l"(g));
}
__device__ __forceinline__ void cp_commit() {
    asm volatile("cp.async.commit_group;" ::: "memory");
}
template<int N>
__device__ __forceinline__ void cp_wait() {
    asm volatile("cp.async.wait_group %0;" :: "n"(N) : "memory");
}
__device__ __forceinline__ void ldsm4(uint32_t& r0, uint32_t& r1, uint32_t& r2,
                                      uint32_t& r3, uint32_t addr) {
    asm volatile("ldmatrix.sync.aligned.m8n8.x4.shared.b16 {%0,%1,%2,%3}, [%4];"
                 : "=r"(r0), "=r"(r1), "=r"(r2), "=r"(r3) : "r"(addr));
}
// f32-accumulate HMMA (proven fastest variant, R13)
__device__ __forceinline__ void mma16816(float* c, const uint32_t* a,
                                         uint32_t b0, uint32_t b1) {
    asm volatile("mma.sync.aligned.m16n8k16.row.col.f32.f16.f16.f32 "
                 "{%0,%1,%2,%3}, {%4,%5,%6,%7}, {%8,%9}, {%0,%1,%2,%3};"
                 : "+f"(c[0]), "+f"(c[1]), "+f"(c[2]), "+f"(c[3])
                 : "r"(a[0]), "r"(a[1]), "r"(a[2]), "r"(a[3]), "r"(b0), "r"(b1));
}
__device__ __forceinline__ float2 ld2f(const float* p) { return *reinterpret_cast<const float2*>(p); }
__device__ __forceinline__ float4 ld4(const float* p)  { return *reinterpret_cast<const float4*>(p); }
__device__ __forceinline__ float2 ld2h(const __half* p) {
    return __half22float2(*reinterpret_cast<const __half2*>(p));
}
__device__ __forceinline__ float sigmf(float x) { return __fdividef(1.0f, 1.0f + __expf(-x)); }
__device__ __forceinline__ float tanhfast(float x) {
    return 1.0f - __fdividef(2.0f, __expf(2.0f * x) + 1.0f);
}
__device__ __forceinline__ float gru_one(float fr, float gr, float fz, float gz,
                                         float fn, float gn, float hp) {
    float r = sigmf(fr + gr);
    float z = sigmf(fz + gz);
    float n = tanhfast(fn + r * gn);
    return n + z * (hp - n);
}

// ================= step GEMM: f32-acc HMMA, fp16 state carry =================
// 256 threads, 8 warps (4m x 2n). CTA tile: 128 rows x 64 cols x 3 gates. K'=512.
// Ain doubles as the MMA A operand AND the previous hidden state hp (fp16).
// MODE 1: h_{t+1} -> fp16 oA only.
// MODE 2: final h -> fp16 eft (oA) + FUSED attention logit (this CTA's 64 cols
//         are exactly head blockIdx.x; per-row dot via smem reduction).
#define SHS    72                        // smem row stride (halves), 144 B
#define SABUF  (128 * SHS * 2)           // 18432 B
#define SBUF   (320 * SHS * 2)           // 46080 B
#define SSMEM  (2 * SBUF)                // 92160 B -> 2 CTAs/SM

template<int MODE>
__global__ void __launch_bounds__(256, 2)
step_gemm(const __half* __restrict__ Ain,
          const __half* __restrict__ Bp,
          const float* __restrict__ bias,
          const int* __restrict__ mp,
          const int* __restrict__ dst,
          const float* __restrict__ attnw,
          __half* __restrict__ oA,
          int M, int t)
{
    extern __shared__ char sm[];
    const uint32_t sbase = smem_u32(sm);

    const int tid  = threadIdx.x;
    const int wid  = tid >> 5;
    const int lane = tid & 31;
    const int nb   = blockIdx.x * 64;
    const int mb   = blockIdx.y * 128;
    const int wq = wid >> 1;             // m quarter
    const int wn = wid & 1;              // n half (32 cols)

    float acc[3][2][4][4];
    #pragma unroll
    for (int g = 0; g < 3; ++g)
        #pragma unroll
        for (int i = 0; i < 2; ++i)
            #pragma unroll
            for (int j = 0; j < 4; ++j)
                #pragma unroll
                for (int c = 0; c < 4; ++c) acc[g][i][j][c] = 0.f;

    auto stage = [&](int kt) {
        const uint32_t ab = sbase + (kt & 1) * SBUF;
        const int kcol = kt * 64;
        #pragma unroll
        for (int it = 0; it < 10; ++it) {
            int i = tid + it * 256;      // 0..2559 (320 rows x 8 chunks)
            if (i < 1024) {
                int row = i >> 3, c = i & 7;
                int gr = mb + row; if (gr >= M) gr = M - 1;
                cp16(ab + (row * SHS + c * 8) * 2, &Ain[(size_t)gr * HD + kcol + c * 8]);
            } else {
                int j = i - 1024;
                int lr = j >> 3, c = j & 7;
                int grow = (lr >> 6) * 512 + nb + (lr & 63);
                cp16(ab + SABUF + (lr * SHS + c * 8) * 2,
                     &Bp[(size_t)grow * HD + kcol + c * 8]);
            }
        }
        cp_commit();
    };

    stage(0);
    for (int kt = 0; kt < 8; ++kt) {
        cp_wait<0>();
        __syncthreads();
        if (kt + 1 < 8) stage(kt + 1);

        const uint32_t ab = sbase + (kt & 1) * SBUF;
        const uint32_t bb = ab + SABUF;
        const int lr16 = lane & 15;
        const int koff = (lane >> 4) << 3;

        #pragma unroll
        for (int kk = 0; kk < 64; kk += 16) {
            uint32_t af[2][4];
            #pragma unroll
            for (int ma = 0; ma < 2; ++ma) {
                uint32_t a = ab + ((wq * 32 + ma * 16 + lr16) * SHS + kk + koff) * 2;
                ldsm4(af[ma][0], af[ma][1], af[ma][2], af[ma][3], a);
            }
            #pragma unroll
            for (int g = 0; g < 3; ++g) {
                #pragma unroll
                for (int np = 0; np < 2; ++np) {
                    uint32_t b0, b1, b2, b3;
                    uint32_t a = bb + ((g * 64 + wn * 32 + np * 16 + lr16) * SHS
                                       + kk + koff) * 2;
                    ldsm4(b0, b1, b2, b3, a);
                    #pragma unroll
                    for (int ma = 0; ma < 2; ++ma) {
                        mma16816(acc[g][ma][np * 2 + 0], af[ma], b0, b2);
                        mma16816(acc[g][ma][np * 2 + 1], af[ma], b1, b3);
                    }
                }
            }
        }
    }

    // ---- fused GRU epilogue ----
    float* s_logit = reinterpret_cast<float*>(sm);   // buffer0 region, safe post-loop
    if (MODE == 2) {
        if (tid < 128) s_logit[tid] = 0.f;
        __syncthreads();
    }

    const int gq  = lane >> 2;
    const int tig = lane & 3;
    #pragma unroll
    for (int ma = 0; ma < 2; ++ma) {
        #pragma unroll
        for (int p = 0; p < 2; ++p) {
            const int mrow = wq * 32 + ma * 16 + gq + p * 8;
            const int m = mb + mrow;
            if (m >= M) continue;
            const int node = mp[m * 3 + t];
            const __half* Fp = &g_F[(size_t)node * G3];
            float part = 0.f;
            #pragma unroll
            for (int na = 0; na < 4; ++na) {
                const int j = nb + wn * 32 + na * 8 + tig * 2;
                float vr0 = acc[0][ma][na][p * 2], vr1 = acc[0][ma][na][p * 2 + 1];
                float vz0 = acc[1][ma][na][p * 2], vz1 = acc[1][ma][na][p * 2 + 1];
                float vn0 = acc[2][ma][na][p * 2], vn1 = acc[2][ma][na][p * 2 + 1];
                float2 br = ld2f(&bias[j]);
                float2 bz = ld2f(&bias[512 + j]);
                float2 bn = ld2f(&bias[1024 + j]);
                float2 fr = ld2h(&Fp[j]);
                float2 fz = ld2h(&Fp[512 + j]);
                float2 fn = ld2h(&Fp[1024 + j]);
                float2 hp = ld2h(&Ain[(size_t)m * HD + j]);   // fp16 state carry
                float h0 = gru_one(fr.x, vr0 + br.x, fz.x, vz0 + bz.x,
                                   fn.x, vn0 + bn.x, hp.x);
                float h1 = gru_one(fr.y, vr1 + br.y, fz.y, vz1 + bz.y,
                                   fn.y, vn1 + bn.y, hp.y);
                *reinterpret_cast<__half2*>(&oA[(size_t)m * HD + j]) =
                    __floats2half2_rn(h0, h1);
                if (MODE == 2) {
                    float2 aw = ld2f(&attnw[j]);     // attnw flat [512] == hidden col
                    part += h0 * aw.x + h1 * aw.y;
                }
            }
            if (MODE == 2) atomicAdd(&s_logit[mrow], part);
        }
    }

    if (MODE == 2) {
        __syncthreads();
        if (tid < 128) {
            int e = mb + tid;
            if (e < M) {
                const int hh = nb >> 6;           // this CTA's head
                float a  = s_logit[tid];
                a = a > 0.f ? a : 0.01f * a;      // leaky relu
                float ex = __expf(a);             // logits bounded (validated R5-R16)
                g_aexp[(size_t)e * HHn + hh] = ex;
                atomicAdd(&g_asum[(size_t)dst[e] * HHn + hh], ex);
            }
        }
    }
}

// ================= F-GEMM (2-term fp16): F = fl16(x) @ fl16(Wih)^T + b_ih =================
// A' = [Xh | Xl], B' = [Wh | Wh]; K'=128, 2 tiles of 64.
#define FHS    72
#define FABUF  (128 * FHS * 2)
#define FBUFB  (320 * FHS * 2)
#define FSMEM  (2 * FBUFB)

__global__ void __launch_bounds__(256, 2)
fgemm(const __half* __restrict__ Xh,
      const __half* __restrict__ Xl,
      const __half* __restrict__ Bp,
      const float* __restrict__ bias,
      __half* __restrict__ outF, int M)
{
    extern __shared__ char sm[];
    const uint32_t sbase = smem_u32(sm);

    const int tid  = threadIdx.x;
    const int wid  = tid >> 5;
    const int lane = tid & 31;
    const int nb   = blockIdx.x * 64;
    const int mb   = blockIdx.y * 128;
    const int wq = wid >> 1;
    const int wn = wid & 1;

    float acc[3][2][4][4];
    #pragma unroll
    for (int g = 0; g < 3; ++g)
        #pragma unroll
        for (int i = 0; i < 2; ++i)
            #pragma unroll
            for (int j = 0; j < 4; ++j)
                #pragma unroll
                for (int c = 0; c < 4; ++c) acc[g][i][j][c] = 0.f;

    auto stage = [&](int kt) {
        const __half* As = (kt == 1) ? Xl : Xh;
        const uint32_t ab = sbase + (kt & 1) * FBUFB;
        #pragma unroll
        for (int it = 0; it < 10; ++it) {
            int i = tid + it * 256;
            if (i < 1024) {
                int row = i >> 3, c = i & 7;
                int gr = mb + row; if (gr >= M) gr = M - 1;
                cp16(ab + (row * FHS + c * 8) * 2, &As[(size_t)gr * DF + c * 8]);
            } else {
                int j = i - 1024;
                int lr = j >> 3, c = j & 7;
                int grow = (lr >> 6) * 512 + nb + (lr & 63);
                cp16(ab + FABUF + (lr * FHS + c * 8) * 2,
                     &Bp[(size_t)grow * 128 + kt * 64 + c * 8]);
            }
        }
        cp_commit();
    };

    stage(0);
    for (int kt = 0; kt < 2; ++kt) {
        cp_wait<0>();
        __syncthreads();
        if (kt + 1 < 2) stage(kt + 1);
        const uint32_t ab = sbase + (kt & 1) * FBUFB;
        const uint32_t bb = ab + FABUF;
        const int lr16 = lane & 15;
        const int koff = (lane >> 4) << 3;
        #pragma unroll
        for (int kk = 0; kk < 64; kk += 16) {
            uint32_t af[2][4];
            #pragma unroll
            for (int ma = 0; ma < 2; ++ma) {
                uint32_t a = ab + ((wq * 32 + ma * 16 + lr16) * FHS + kk + koff) * 2;
                ldsm4(af[ma][0], af[ma][1], af[ma][2], af[ma][3], a);
            }
            #pragma unroll
            for (int g = 0; g < 3; ++g) {
                #pragma unroll
                for (int np = 0; np < 2; ++np) {
                    uint32_t b0, b1, b2, b3;
                    uint32_t a = bb + ((g * 64 + wn * 32 + np * 16 + lr16) * FHS
                                       + kk + koff) * 2;
                    ldsm4(b0, b1, b2, b3, a);
                    #pragma unroll
                    for (int ma = 0; ma < 2; ++ma) {
                        mma16816(acc[g][ma][np * 2 + 0], af[ma], b0, b2);
                        mma16816(acc[g][ma][np * 2 + 1], af[ma], b1, b3);
                    }
                }
            }
        }
    }

    const int gq  = lane >> 2;
    const int tig = lane & 3;
    #pragma unroll
    for (int ma = 0; ma < 2; ++ma) {
        #pragma unroll
        for (int p = 0; p < 2; ++p) {
            const int m = mb + wq * 32 + ma * 16 + gq + p * 8;
            if (m >= M) continue;
            #pragma unroll
            for (int na = 0; na < 4; ++na) {
                const int j = nb + wn * 32 + na * 8 + tig * 2;
                float2 br = ld2f(&bias[j]);
                float2 bz = ld2f(&bias[512 + j]);
                float2 bn = ld2f(&bias[1024 + j]);
                *reinterpret_cast<__half2*>(&outF[(size_t)m * G3 + j]) =
                    __floats2half2_rn(acc[0][ma][na][p*2] + br.x, acc[0][ma][na][p*2+1] + br.y);
                *reinterpret_cast<__half2*>(&outF[(size_t)m * G3 + 512 + j]) =
                    __floats2half2_rn(acc[1][ma][na][p*2] + bz.x, acc[1][ma][na][p*2+1] + bz.y);
                *reinterpret_cast<__half2*>(&outF[(size_t)m * G3 + 1024 + j]) =
                    __floats2half2_rn(acc[2][ma][na][p*2] + bn.x, acc[2][ma][na][p*2+1] + bn.y);
            }
        }
    }
}

// ================= elementwise kernels =================
__global__ void zero_kernel(float* __restrict__ out, int nOut, int nSum) {
    int stride = gridDim.x * blockDim.x;
    int i0 = blockIdx.x * blockDim.x + threadIdx.x;
    for (int i = i0; i < nOut; i += stride) out[i] = 0.0f;
    for (int i = i0; i < nSum; i += stride) g_asum[i] = 0.0f;
}

__global__ void split_kernel(const float* __restrict__ feat,
                             const float* __restrict__ Whh,
                             const float* __restrict__ Wih, int nodes) {
    int stride = gridDim.x * blockDim.x;
    int i0 = blockIdx.x * blockDim.x + threadIdx.x;
    for (int i = i0; i < nodes * DF; i += stride) {
        __half h = __float2half_rn(feat[i]);
        __half l = __float2half_rn(feat[i] - __half2float(h));
        g_Xh[i] = h;
        g_Xl[i] = l;
    }
    for (int i = i0; i < G3 * HD; i += stride)
        g_Bhh[i] = __float2half_rn(Whh[i]);
    for (int i = i0; i < G3 * DF; i += stride) {
        int n = i >> 6, k = i & 63;
        __half h = __float2half_rn(Wih[i]);
        size_t b = (size_t)n * 128;
        g_Bih[b + k]      = h;
        g_Bih[b + 64 + k] = h;
    }
}

// step 0: h1 = gru(F[node0], b_hh, h=0); write fp16 g_Ah0 only
__global__ void step0_kernel(const int* __restrict__ mp,
                             const float* __restrict__ bhh, int E) {
    int i = blockIdx.x * blockDim.x + threadIdx.x;
    if (i >= E * (HD / 4)) return;
    int e = i >> 7, c4 = (i & 127) << 2;
    int node = mp[e * 3];
    const __half* Fp = &g_F[(size_t)node * G3];
    float2 fr0 = ld2h(Fp + c4),        fr1 = ld2h(Fp + c4 + 2);
    float2 fz0 = ld2h(Fp + 512 + c4),  fz1 = ld2h(Fp + 512 + c4 + 2);
    float2 fn0 = ld2h(Fp + 1024 + c4), fn1 = ld2h(Fp + 1024 + c4 + 2);
    float4 br = ld4(bhh + c4), bz = ld4(bhh + 512 + c4), bn = ld4(bhh + 1024 + c4);
    float h0 = gru_one(fr0.x, br.x, fz0.x, bz.x, fn0.x, bn.x, 0.f);
    float h1 = gru_one(fr0.y, br.y, fz0.y, bz.y, fn0.y, bn.y, 0.f);
    float h2 = gru_one(fr1.x, br.z, fz1.x, bz.z, fn1.x, bn.z, 0.f);
    float h3 = gru_one(fr1.y, br.w, fz1.y, bz.w, fn1.y, bn.w, 0.f);
    *reinterpret_cast<__half2*>(&g_Ah0[(size_t)e * HD + c4])     = __floats2half2_rn(h0, h1);
    *reinterpret_cast<__half2*>(&g_Ah0[(size_t)e * HD + c4 + 2]) = __floats2half2_rn(h2, h3);
}

// alpha scale + scatter-sum into output (eft fp16)
__global__ void finalize_kernel(const int* __restrict__ dst,
                                const __half* __restrict__ eft,
                                float* __restrict__ out, int E) {
    int i = blockIdx.x * blockDim.x + threadIdx.x;
    if (i >= E * (HD / 4)) return;
    int e = i >> 7, c4 = (i & 127) << 2;
    int hh = c4 >> 6;
    int dd = dst[e];
    float alpha = __fdividef(g_aexp[(size_t)e * HHn + hh],
                             g_asum[(size_t)dd * HHn + hh]);
    float2 v0 = ld2h(&eft[(size_t)e * HD + c4]);
    float2 v1 = ld2h(&eft[(size_t)e * HD + c4 + 2]);
    float* o = &out[(size_t)dd * HD + c4];
    atomicAdd(o + 0, v0.x * alpha);
    atomicAdd(o + 1, v0.y * alpha);
    atomicAdd(o + 2, v1.x * alpha);
    atomicAdd(o + 3, v1.y * alpha);
}

// ================= launcher =================
extern "C" void kernel_launch(void* const* d_in, const int* in_sizes, int n_in,
                              void* d_out, int out_size) {
    const float* feat  = (const float*)d_in[0];
    const float* Wih   = (const float*)d_in[1];
    const float* Whh   = (const float*)d_in[2];
    const float* bih   = (const float*)d_in[3];
    const float* bhh   = (const float*)d_in[4];
    const float* attnw = (const float*)d_in[5];
    const int* mp_idx  = (const int*)d_in[6];
    const int* dst     = (const int*)d_in[7];
    const int E     = in_sizes[7];
    const int nodes = in_sizes[0] / DF;
    float* out = (float*)d_out;
    const int nd8 = (out_size / HD) * HHn;

    __half *pF, *pXh, *pXl, *pAh0, *pAh1, *pBhh, *pBih;
    cudaGetSymbolAddress((void**)&pF,   g_F);
    cudaGetSymbolAddress((void**)&pXh,  g_Xh);
    cudaGetSymbolAddress((void**)&pXl,  g_Xl);
    cudaGetSymbolAddress((void**)&pAh0, g_Ah0);
    cudaGetSymbolAddress((void**)&pAh1, g_Ah1);
    cudaGetSymbolAddress((void**)&pBhh, g_Bhh);
    cudaGetSymbolAddress((void**)&pBih, g_Bih);

    cudaFuncSetAttribute(fgemm,        cudaFuncAttributeMaxDynamicSharedMemorySize, FSMEM);
    cudaFuncSetAttribute(step_gemm<1>, cudaFuncAttributeMaxDynamicSharedMemorySize, SSMEM);
    cudaFuncSetAttribute(step_gemm<2>, cudaFuncAttributeMaxDynamicSharedMemorySize, SSMEM);

    zero_kernel<<<2048, 256>>>(out, out_size, nd8);
    split_kernel<<<2048, 256>>>(feat, Whh, Wih, nodes);

    // F = fl16(x) @ fl16(Wih)^T + b_ih over nodes (2-term, K'=128)
    dim3 gF(8, (nodes + 127) / 128);
    fgemm<<<gF, 256, FSMEM>>>(pXh, pXl, pBih, bih, pF, nodes);

    const int ew = (E * (HD / 4) + 255) / 256;
    step0_kernel<<<ew, 256>>>(mp_idx, bhh, E);

    dim3 gE(8, (E + 127) / 128);
    // step 1: gh = fl16(h1)@Whh^T + b_hh; hp = fp16 Ah0; writes fl16 h2 -> Ah1
    step_gemm<1><<<gE, 256, SSMEM>>>(pAh0, pBhh, bhh, mp_idx, dst, attnw,
                                     pAh1, E, 1);
    // step 2: hp = fp16 Ah1; final h -> fp16 eft (reuse Ah0) + fused logits
    step_gemm<2><<<gE, 256, SSMEM>>>(pAh1, pBhh, bhh, mp_idx, dst, attnw,
                                     pAh0, E, 2);

    finalize_kernel<<<ew, 256>>>(dst, pAh0, out, E);
}